// round 13
// baseline (speedup 1.0000x reference)
#include <cuda_runtime.h>
#include <cuda_fp16.h>
#include <cstdint>

#define NUM_LAYERS 16
#define KS 31
#define HH 1024
#define WW 1024
#define IMW 1054          // 1024 + 31 - 1
#define NC 3
#define TAPS (KS * KS)    // 961
#define TDIM 256
#define XT 8              // x-tiles of 8 px -> 64 px per block
#define SROW 96           // smem pair-row stride (u32), indices 0..94 used
#define NROWS 38          // 8 y-rows + 30 halo

// dynamic smem layout (bytes): [0, 16896) = pairs (14592 B) aliased with dsm
// (16896 B, used only after ky loop); [16896, 48640) = A-fragment cache
#define PAIRS_WORDS (NROWS * SROW)            // 3648 u32 = 14592 B
#define UNION_BYTES 16896                     // max(pairs, dsm 8*16*33*4)
#define WF_OFF  UNION_BYTES
#define WF_ELEMS (KS * 2 * 32)                // 1984 uint4 = 31744 B
#define SMEM_BYTES (WF_OFF + WF_ELEMS * 16)   // 48640

// weights pre-packed as per-lane m16n8k16 f16 A-fragments:
// [c][ky][slice(2)][lane] -> uint4 {a0,a1,a2,a3} (each a f16x2)
__device__ uint4 g_wfrag[NC * KS * 2 * 32];

__device__ __forceinline__ void mma16(float* d, uint32_t a0, uint32_t a1,
                                      uint32_t a2, uint32_t a3,
                                      uint32_t b0, uint32_t b1) {
    asm volatile(
        "mma.sync.aligned.m16n8k16.row.col.f32.f16.f16.f32 "
        "{%0,%1,%2,%3}, {%4,%5,%6,%7}, {%8,%9}, {%0,%1,%2,%3};"
        : "+f"(d[0]), "+f"(d[1]), "+f"(d[2]), "+f"(d[3])
        : "r"(a0), "r"(a1), "r"(a2), "r"(a3), "r"(b0), "r"(b1));
}

__device__ __forceinline__ uint32_t pack_h2(float lo, float hi) {
    __half2 h = __halves2half2(__float2half_rn(lo), __float2half_rn(hi));
    return *(uint32_t*)&h;
}

// Pack weights into m16n8k16 f16 A-fragment order (M=16 layers, K=16 taps/slice).
__global__ void prep_w(const float* __restrict__ w) {
    int i = blockIdx.x * blockDim.x + threadIdx.x;
    if (i >= NC * KS * 2 * 32) return;
    int lane = i & 31;
    int s    = (i >> 5) & 1;
    int ky   = (i >> 6) % KS;
    int c    = i / (KS * 2 * 32);
    int g = lane >> 2, t = lane & 3;
    const float* wc = w + (size_t)c * NUM_LAYERS * TAPS + (size_t)ky * KS;
    auto W = [&](int l, int k) -> float {
        int kx = 16 * s + k;
        return (kx < KS) ? wc[(size_t)l * TAPS + kx] : 0.0f;
    };
    uint4 v;
    v.x = pack_h2(W(g,     2 * t),     W(g,     2 * t + 1));
    v.y = pack_h2(W(g + 8, 2 * t),     W(g + 8, 2 * t + 1));
    v.z = pack_h2(W(g,     2 * t + 8), W(g,     2 * t + 9));
    v.w = pack_h2(W(g + 8, 2 * t + 8), W(g + 8, 2 * t + 9));
    g_wfrag[i] = v;
}

__global__ void __launch_bounds__(TDIM, 3)
blur_mma(const float* __restrict__ img, const int* __restrict__ idxp,
         const float* __restrict__ alpha, float* __restrict__ out)
{
    extern __shared__ char smem[];
    uint32_t* pairs = (uint32_t*)smem;                    // f16x2 pair table
    float*    dsm   = (float*)smem;                       // aliased after ky loop
    uint4*    wfs   = (uint4*)(smem + WF_OFF);            // A-fragments in smem

    const int c  = blockIdx.z;
    const int x0 = blockIdx.x * 64;
    const int y0 = blockIdx.y * 8;
    const int tid = threadIdx.x, wid = tid >> 5, lane = tid & 31;
    const int g = lane >> 2, t = lane & 3;

    // stage A-fragments for this channel into smem (L2-hot)
    const uint4* wfg = g_wfrag + (size_t)c * WF_ELEMS;
    for (int i = tid; i < WF_ELEMS; i += TDIM) wfs[i] = wfg[i];

    // stage image patch as overlapping half2 pairs (38 rows x 95 pair-words)
    const float* ims = img + (size_t)c * IMW * IMW + (size_t)y0 * IMW + x0;
    for (int i = tid; i < NROWS * SROW; i += TDIM) {
        int r = i / SROW, cc = i - r * SROW;
        float a = (cc < 95 && x0 + cc     < IMW) ? __ldg(ims + (size_t)r * IMW + cc)     : 0.0f;
        float b = (cc < 94 && x0 + cc + 1 < IMW) ? __ldg(ims + (size_t)r * IMW + cc + 1) : 0.0f;
        pairs[i] = pack_h2(a, b);
    }
    __syncthreads();

    float acc[XT][4];
    #pragma unroll
    for (int xt = 0; xt < XT; ++xt)
        acc[xt][0] = acc[xt][1] = acc[xt][2] = acc[xt][3] = 0.0f;

    // per-warp ky rotation: decorrelate loop-head stalls across SMSP warps
    const int kyw = (wid * 4) % KS;

    for (int kk = 0; kk < KS; ++kk) {
        int ky = kyw + kk; if (ky >= KS) ky -= KS;

        // A fragments from smem (conflict-free LDS.128)
        uint4 A0 = wfs[(ky * 2 + 0) * 32 + lane];
        uint4 A1 = wfs[(ky * 2 + 1) * 32 + lane];

        // B ring: B0(j) = pairs[row][8j + g + 2t]; frag F(j) = {B0(j), B0(j+1)}
        const uint32_t* rp = pairs + (wid + ky) * SROW + g + 2 * t;
        uint32_t B0[4];
        #pragma unroll
        for (int j = 0; j < 4; ++j) B0[j] = rp[8 * j];

        #pragma unroll
        for (int xt = 0; xt < XT; ++xt) {
            // slice 0: F(xt), slice 1: F(xt+2)
            mma16(acc[xt], A0.x, A0.y, A0.z, A0.w,
                  B0[xt & 3], B0[(xt + 1) & 3]);
            mma16(acc[xt], A1.x, A1.y, A1.z, A1.w,
                  B0[(xt + 2) & 3], B0[(xt + 3) & 3]);
            if (xt < XT - 1)                   // slot xt&3 -> B0(xt+4), max B0(10)
                B0[xt & 3] = rp[8 * (xt + 4)];
        }
    }
    __syncthreads();   // all warps done reading pairs; dsm may now alias it

    // ---- epilogue: out[c,y,x] = sum_l D[l,x] * alpha[idx,l,y,x] ----
    const int idx = *idxp;
    const int y = y0 + wid;
    float* dw = dsm + wid * (16 * 33);
    #pragma unroll
    for (int ch = 0; ch < 2; ++ch) {          // 2 chunks of 32 px
        #pragma unroll
        for (int q = 0; q < 4; ++q) {
            int xt = ch * 4 + q;
            int xl = q * 8 + 2 * t;
            dw[g * 33 + xl]           = acc[xt][0];
            dw[g * 33 + xl + 1]       = acc[xt][1];
            dw[(g + 8) * 33 + xl]     = acc[xt][2];
            dw[(g + 8) * 33 + xl + 1] = acc[xt][3];
        }
        __syncwarp();
        const int xo = x0 + ch * 32 + lane;
        const float* ap = alpha + (((size_t)idx * NUM_LAYERS) * HH + y) * WW + xo;
        float s = 0.0f;
        #pragma unroll
        for (int l = 0; l < NUM_LAYERS; ++l)
            s += dw[l * 33 + lane] * __ldg(ap + (size_t)l * (HH * WW));
        out[((size_t)c * HH + y) * WW + xo] = s;
        __syncwarp();
    }
}

extern "C" void kernel_launch(void* const* d_in, const int* in_sizes, int n_in,
                              void* d_out, int out_size) {
    const float* img   = (const float*)d_in[0];
    const int*   idxp  = (const int*)d_in[1];
    const float* w     = (const float*)d_in[2];
    const float* alpha = (const float*)d_in[3];
    float*       out   = (float*)d_out;

    prep_w<<<(NC * KS * 2 * 32 + 255) / 256, 256>>>(w);

    cudaFuncSetAttribute(blur_mma,
                         cudaFuncAttributeMaxDynamicSharedMemorySize, SMEM_BYTES);
    dim3 grid(WW / 64, HH / 8, NC);
    blur_mma<<<grid, TDIM, SMEM_BYTES>>>(img, idxp, alpha, out);
}

// round 14
// speedup vs baseline: 1.1718x; 1.1718x over previous
#include <cuda_runtime.h>
#include <cuda_fp16.h>
#include <cstdint>

#define NUM_LAYERS 16
#define KS 31
#define HH 1024
#define WW 1024
#define IMW 1054          // 1024 + 31 - 1
#define NC 3
#define TAPS (KS * KS)    // 961
#define TDIM 256
#define XT 16             // x-tiles of 8 px -> 128 px per block
#define SROW 160          // smem pair-row stride (u32)
#define NROWS 38          // 8 y-rows + 30 halo
#define PW 1056           // global pair-table row stride (u32), 16B-aligned

// dynamic smem layout (bytes)
#define PAIRS_WORDS (NROWS * SROW)            // 6080 u32 = 24320 B
#define WF_OFF  (PAIRS_WORDS * 4)             // 24320
#define WF_ELEMS (KS * 2 * 32)                // 1984 uint4 = 31744 B
#define DSM_OFF (WF_OFF + WF_ELEMS * 16)      // 56064
#define SMEM_BYTES (DSM_OFF + 8 * 16 * 33 * 4)  // 72960

// global pair table: [c][row][cc] = pack_h2(img[c][row][cc], img[c][row][cc+1])
__device__ uint32_t g_pairs[NC * IMW * PW];
// weights pre-packed as per-lane m16n8k16 f16 A-fragments
__device__ uint4 g_wfrag[NC * KS * 2 * 32];

__device__ __forceinline__ void mma16(float* d, uint32_t a0, uint32_t a1,
                                      uint32_t a2, uint32_t a3,
                                      uint32_t b0, uint32_t b1) {
    asm volatile(
        "mma.sync.aligned.m16n8k16.row.col.f32.f16.f16.f32 "
        "{%0,%1,%2,%3}, {%4,%5,%6,%7}, {%8,%9}, {%0,%1,%2,%3};"
        : "+f"(d[0]), "+f"(d[1]), "+f"(d[2]), "+f"(d[3])
        : "r"(a0), "r"(a1), "r"(a2), "r"(a3), "r"(b0), "r"(b1));
}

__device__ __forceinline__ uint32_t pack_h2(float lo, float hi) {
    __half2 h = __halves2half2(__float2half_rn(lo), __float2half_rn(hi));
    return *(uint32_t*)&h;
}

__device__ __forceinline__ void cp_async16(uint32_t dst_smem, const void* src) {
    asm volatile("cp.async.cg.shared.global [%0], [%1], 16;"
                 :: "r"(dst_smem), "l"(src) : "memory");
}
__device__ __forceinline__ uint32_t smem_u32(const void* p) {
    uint32_t a;
    asm("{ .reg .u64 t; cvta.to.shared.u64 t, %1; cvt.u32.u64 %0, t; }" : "=r"(a) : "l"(p));
    return a;
}

// build global pair table
__global__ void prep_pairs(const float* __restrict__ img) {
    int i = blockIdx.x * blockDim.x + threadIdx.x;
    if (i >= NC * IMW * PW) return;
    int c   = i / (IMW * PW);
    int rem = i - c * (IMW * PW);
    int r   = rem / PW;
    int cc  = rem - r * PW;
    const float* ip = img + (size_t)c * IMW * IMW + (size_t)r * IMW;
    float a = (cc     < IMW) ? ip[cc]     : 0.0f;
    float b = (cc + 1 < IMW) ? ip[cc + 1] : 0.0f;
    g_pairs[i] = pack_h2(a, b);
}

// Pack weights into m16n8k16 f16 A-fragment order (M=16 layers, K=16 taps/slice).
__global__ void prep_w(const float* __restrict__ w) {
    int i = blockIdx.x * blockDim.x + threadIdx.x;
    if (i >= NC * KS * 2 * 32) return;
    int lane = i & 31;
    int s    = (i >> 5) & 1;
    int ky   = (i >> 6) % KS;
    int c    = i / (KS * 2 * 32);
    int g = lane >> 2, t = lane & 3;
    const float* wc = w + (size_t)c * NUM_LAYERS * TAPS + (size_t)ky * KS;
    auto W = [&](int l, int k) -> float {
        int kx = 16 * s + k;
        return (kx < KS) ? wc[(size_t)l * TAPS + kx] : 0.0f;
    };
    uint4 v;
    v.x = pack_h2(W(g,     2 * t),     W(g,     2 * t + 1));
    v.y = pack_h2(W(g + 8, 2 * t),     W(g + 8, 2 * t + 1));
    v.z = pack_h2(W(g,     2 * t + 8), W(g,     2 * t + 9));
    v.w = pack_h2(W(g + 8, 2 * t + 8), W(g + 8, 2 * t + 9));
    g_wfrag[i] = v;
}

__global__ void __launch_bounds__(TDIM, 2)
blur_mma(const int* __restrict__ idxp,
         const float* __restrict__ alpha, float* __restrict__ out)
{
    extern __shared__ char smem[];
    uint32_t* pairs = (uint32_t*)smem;                    // f16x2 pair table tile
    uint4*    wfs   = (uint4*)(smem + WF_OFF);            // A-fragments in smem
    float*    dsm   = (float*)(smem + DSM_OFF);           // [8][16][33] transpose buf

    const int c  = blockIdx.z;
    const int x0 = blockIdx.x * 128;
    const int y0 = blockIdx.y * 8;
    const int tid = threadIdx.x, wid = tid >> 5, lane = tid & 31;
    const int g = lane >> 2, t = lane & 3;

    // ---- async stage: pairs tile (38 rows x 160 words = 1520 chunks) ----
    const uint32_t sb_pairs = smem_u32(pairs);
    const uint32_t* gp = g_pairs + (size_t)c * IMW * PW + (size_t)y0 * PW + x0;
    #pragma unroll
    for (int k = 0; k < 6; ++k) {
        int ch = k * TDIM + tid;            // chunk id
        if (ch < NROWS * (SROW / 4)) {
            int r  = ch / (SROW / 4);
            int cw = (ch - r * (SROW / 4)) * 4;
            cp_async16(sb_pairs + (r * SROW + cw) * 4, gp + (size_t)r * PW + cw);
        }
    }
    // ---- async stage: A-fragment cache (1984 uint4 chunks) ----
    const uint32_t sb_wfs = smem_u32(wfs);
    const uint4* wfg = g_wfrag + (size_t)c * WF_ELEMS;
    #pragma unroll
    for (int k = 0; k < 8; ++k) {
        int i = k * TDIM + tid;
        if (i < WF_ELEMS) cp_async16(sb_wfs + i * 16, wfg + i);
    }
    asm volatile("cp.async.commit_group;" ::: "memory");
    asm volatile("cp.async.wait_group 0;" ::: "memory");
    __syncthreads();

    float acc[XT][4];
    #pragma unroll
    for (int xt = 0; xt < XT; ++xt)
        acc[xt][0] = acc[xt][1] = acc[xt][2] = acc[xt][3] = 0.0f;

    // per-warp ky rotation: decorrelate loop-head stalls across SMSP warps
    const int kyw = (wid * 4) % KS;

    for (int kk = 0; kk < KS; ++kk) {
        int ky = kyw + kk; if (ky >= KS) ky -= KS;

        // A fragments from smem (conflict-free LDS.128)
        uint4 A0 = wfs[(ky * 2 + 0) * 32 + lane];
        uint4 A1 = wfs[(ky * 2 + 1) * 32 + lane];

        // B ring: B0(j) = pairs[row][8j + g + 2t]; frag F(j) = {B0(j), B0(j+1)}
        const uint32_t* rp = pairs + (wid + ky) * SROW + g + 2 * t;
        uint32_t B0[4];
        #pragma unroll
        for (int j = 0; j < 4; ++j) B0[j] = rp[8 * j];

        #pragma unroll
        for (int xt = 0; xt < XT; ++xt) {
            // slice 0: F(xt), slice 1: F(xt+2)
            mma16(acc[xt], A0.x, A0.y, A0.z, A0.w,
                  B0[xt & 3], B0[(xt + 1) & 3]);
            mma16(acc[xt], A1.x, A1.y, A1.z, A1.w,
                  B0[(xt + 2) & 3], B0[(xt + 3) & 3]);
            if (xt < XT - 1)                   // slot xt&3 -> B0(xt+4)
                B0[xt & 3] = rp[8 * (xt + 4)];
        }
    }

    // ---- epilogue: out[c,y,x] = sum_l D[l,x] * alpha[idx,l,y,x] ----
    const int idx = *idxp;
    const int y = y0 + wid;
    float* dw = dsm + wid * (16 * 33);
    #pragma unroll
    for (int ch = 0; ch < 4; ++ch) {          // 4 chunks of 32 px
        #pragma unroll
        for (int q = 0; q < 4; ++q) {
            int xt = ch * 4 + q;
            int xl = q * 8 + 2 * t;
            dw[g * 33 + xl]           = acc[xt][0];
            dw[g * 33 + xl + 1]       = acc[xt][1];
            dw[(g + 8) * 33 + xl]     = acc[xt][2];
            dw[(g + 8) * 33 + xl + 1] = acc[xt][3];
        }
        __syncwarp();
        const int xo = x0 + ch * 32 + lane;
        const float* ap = alpha + (((size_t)idx * NUM_LAYERS) * HH + y) * WW + xo;
        float s = 0.0f;
        #pragma unroll
        for (int l = 0; l < NUM_LAYERS; ++l)
            s += dw[l * 33 + lane] * __ldg(ap + (size_t)l * (HH * WW));
        out[((size_t)c * HH + y) * WW + xo] = s;
        __syncwarp();
    }
}

extern "C" void kernel_launch(void* const* d_in, const int* in_sizes, int n_in,
                              void* d_out, int out_size) {
    const float* img   = (const float*)d_in[0];
    const int*   idxp  = (const int*)d_in[1];
    const float* w     = (const float*)d_in[2];
    const float* alpha = (const float*)d_in[3];
    float*       out   = (float*)d_out;

    prep_w<<<(NC * KS * 2 * 32 + 255) / 256, 256>>>(w);
    prep_pairs<<<(NC * IMW * PW + 255) / 256, 256>>>(img);

    cudaFuncSetAttribute(blur_mma,
                         cudaFuncAttributeMaxDynamicSharedMemorySize, SMEM_BYTES);
    dim3 grid(WW / 128, HH / 8, NC);
    blur_mma<<<grid, TDIM, SMEM_BYTES>>>(idxp, alpha, out);
}